// round 7
// baseline (speedup 1.0000x reference)
#include <cuda_runtime.h>
#include <cstdint>
#include <math.h>

// Problem constants
#define NCHUNK 32
#define NBATCH 64
#define HALF   128
#define SIZE   (2 * HALF)            // 256
#define NROWS  (NCHUNK * NBATCH)     // 2048
#define C_SCALE 1e-4f
#define M_SCALE 1e-5f

#define YDOT_FLOATS (NROWS * SIZE)   // 524288

// J broadcast via TMA bulk stores:
//   16 segments (16KB each, SMEM-staged) x 74 groups = 1184 blocks
//   = EXACTLY 1 wave at 8 blocks/SM x 148 SMs.
//   Each block bulk-copies its SMEM segment to a CONTIGUOUS range of 27-28
//   batch copies; each copy is ONE cp.async.bulk (16KB), issued by a
//   distinct thread -> deep async write queue, no SM store-queue limit.
#define SEGS 16
#define GRPS 74
#define NBLK (SEGS * GRPS)           // 1184
#define SEG_BYTES 16384              // 16KB segment = 4096 floats
#define COPY_BYTES (SIZE * SIZE * 4) // 262144 bytes per J copy

// ---------------------------------------------------------------------------
// Closed-form Jb[r][c] (256x256)
// ---------------------------------------------------------------------------
__device__ __forceinline__ float jb_val(int r, int c,
                                        const float* __restrict__ K,
                                        const float* __restrict__ C,
                                        const float* __restrict__ M) {
    if (r < HALF) {
        return (c == r + HALF) ? 1.0f : 0.0f;
    }
    int i = r - HALF;
    int j = (c < HALF) ? c : (c - HALF);
    int d = j - i;
    if (d < -1 || d > 1) return 0.0f;

    float Mi = M[i] * M_SCALE;
    if (c < HALF) {
        if (d == 0) {
            float v = -K[i] / Mi;
            if (i > 0) v -= K[i - 1] / Mi;
            return v;
        } else if (d == 1) {
            return K[i] / Mi;
        } else {
            return K[i - 1] / Mi;
        }
    } else {
        if (d == 0) {
            float v = -(C[i] * C_SCALE) / Mi;
            if (i > 0) v -= (C[i - 1] * C_SCALE) / Mi;
            return v;
        } else if (d == 1) {
            return (C[i] * C_SCALE) / Mi;
        } else {
            return (C[i - 1] * C_SCALE) / Mi;
        }
    }
}

__device__ __forceinline__ unsigned int smem_u32(const void* p) {
    unsigned int a;
    asm("{ .reg .u64 tmp; cvta.to.shared.u64 tmp, %1; cvt.u32.u64 %0, tmp; }"
        : "=r"(a) : "l"(p));
    return a;
}

// ---------------------------------------------------------------------------
// ONE fused kernel: 1184 blocks x 256 threads (exactly 1 wave at 8/SM).
// ---------------------------------------------------------------------------
__global__ void __launch_bounds__(SIZE, 8)
fused_kernel(const float* __restrict__ t,
             const float* __restrict__ y,
             const float* __restrict__ K,
             const float* __restrict__ C,
             const float* __restrict__ M,
             float* __restrict__ out) {
    __shared__ alignas(16) float4 seg[SEG_BYTES / 16];  // 16KB Jb segment
    __shared__ float sm[SIZE];                           // ydot staging

    int bid = blockIdx.x;
    int tid = threadIdx.x;

    // ---- Fill this block's Jb segment in SMEM -----------------------------
    int s = bid & (SEGS - 1);        // segment 0..15
    int g = bid >> 4;                // group   0..73
    int segFloatBase = s * (SEG_BYTES / 4);   // linear float base in Jb

    #pragma unroll
    for (int q = 0; q < 4; q++) {
        int e = segFloatBase + (q * 256 + tid) * 4;
        int r = e >> 8;
        int c = e & (SIZE - 1);
        float4 v;
        v.x = jb_val(r, c + 0, K, C, M);
        v.y = jb_val(r, c + 1, K, C, M);
        v.z = jb_val(r, c + 2, K, C, M);
        v.w = jb_val(r, c + 3, K, C, M);
        seg[q * 256 + tid] = v;
    }
    __syncthreads();

    // ---- Issue bulk stores: one 16KB cp.async.bulk per copy, one thread
    //      per copy, contiguous copy range ----------------------------------
    int k0 = (g * NROWS) / GRPS;
    int k1 = ((g + 1) * NROWS) / GRPS;    // 27-28 copies
    int nc = k1 - k0;

    char* jbase = reinterpret_cast<char*>(out + YDOT_FLOATS);
    unsigned int saddr = smem_u32(seg);

    if (tid < nc) {
        // order SMEM generic-proxy writes before async-proxy reads
        asm volatile("fence.proxy.async.shared::cta;" ::: "memory");
        char* gdst = jbase + (long long)(k0 + tid) * COPY_BYTES
                           + (long long)s * SEG_BYTES;
        asm volatile(
            "cp.async.bulk.global.shared::cta.bulk_group [%0], [%1], %2;"
            :: "l"(gdst), "r"(saddr), "r"((int)SEG_BYTES) : "memory");
        asm volatile("cp.async.bulk.commit_group;" ::: "memory");
    }

    // ---- ydot rows (overlaps with TMA drain), strided over the grid -------
    for (int row = bid; row < NROWS; row += NBLK) {
        sm[tid] = y[row * SIZE + tid];
        __syncthreads();

        float res;
        if (tid < HALF) {
            res = sm[HALF + tid];                 // ydot[:half] = v
        } else {
            int i = tid - HALF;
            float Mi = M[i] * M_SCALE;
            float acc = 0.0f;
            if (i < HALF - 1) {
                float f = K[i] * (sm[i + 1] - sm[i])
                        + (C[i] * C_SCALE) * (sm[HALF + i + 1] - sm[HALF + i]);
                acc += f / Mi;
            }
            if (i > 0) {
                float fm = K[i - 1] * (sm[i] - sm[i - 1])
                         + (C[i - 1] * C_SCALE) * (sm[HALF + i] - sm[HALF + i - 1]);
                acc -= fm / Mi;
            }
            if (i == HALF - 1) {
                acc -= (K[HALF - 1] * sm[HALF - 1]
                      + (C[HALF - 1] * C_SCALE) * sm[SIZE - 1]) / Mi;
            }
            if (i == 0) {
                acc += sinf(t[row]) / Mi;
            }
            res = acc;
        }
        out[row * SIZE + tid] = res;
        __syncthreads();   // protect sm before next iteration
    }

    // ---- Drain this thread's bulk-store group before exit -----------------
    if (tid < nc) {
        asm volatile("cp.async.bulk.wait_group 0;" ::: "memory");
    }
}

// ---------------------------------------------------------------------------
extern "C" void kernel_launch(void* const* d_in, const int* in_sizes, int n_in,
                              void* d_out, int out_size) {
    const float* t = (const float*)d_in[0];
    const float* y = (const float*)d_in[1];
    const float* K = (const float*)d_in[2];
    const float* C = (const float*)d_in[3];
    const float* M = (const float*)d_in[4];
    float* out = (float*)d_out;

    fused_kernel<<<NBLK, SIZE>>>(t, y, K, C, M, out);
}

// round 8
// speedup vs baseline: 1.0400x; 1.0400x over previous
#include <cuda_runtime.h>
#include <math.h>

// Problem constants
#define NCHUNK 32
#define NBATCH 64
#define HALF   128
#define SIZE   (2 * HALF)            // 256
#define NROWS  (NCHUNK * NBATCH)     // 2048
#define C_SCALE 1e-4f
#define M_SCALE 1e-5f

#define YDOT_FLOATS (NROWS * SIZE)   // 524288

// R2's measured-best mapping: 16 segments x 128 groups = 2048 blocks.
// Each block holds one 16KB segment (4 float4/thread in registers) and
// writes it to 16 CONTIGUOUS batch copies. The 16-copy loop is FULLY
// unrolled: all 64 STG.128 per thread are independent stores off a single
// base register with immediate offsets (16 copies span 4MB < STG imm range).
#define SEGS 16
#define GRP  128
#define NBLK (SEGS * GRP)            // 2048
#define CPB  (NROWS / GRP)           // 16 copies per block
#define SEG_F4 1024                  // float4 per segment
#define COPY_F4 16384                // float4 per J copy

// ---------------------------------------------------------------------------
// Closed-form Jb[r][c] (256x256)
// ---------------------------------------------------------------------------
__device__ __forceinline__ float jb_val(int r, int c,
                                        const float* __restrict__ K,
                                        const float* __restrict__ C,
                                        const float* __restrict__ M) {
    if (r < HALF) {
        return (c == r + HALF) ? 1.0f : 0.0f;
    }
    int i = r - HALF;
    int j = (c < HALF) ? c : (c - HALF);
    int d = j - i;
    if (d < -1 || d > 1) return 0.0f;

    float Mi = M[i] * M_SCALE;
    if (c < HALF) {
        if (d == 0) {
            float v = -K[i] / Mi;
            if (i > 0) v -= K[i - 1] / Mi;
            return v;
        } else if (d == 1) {
            return K[i] / Mi;
        } else {
            return K[i - 1] / Mi;
        }
    } else {
        if (d == 0) {
            float v = -(C[i] * C_SCALE) / Mi;
            if (i > 0) v -= (C[i - 1] * C_SCALE) / Mi;
            return v;
        } else if (d == 1) {
            return (C[i] * C_SCALE) / Mi;
        } else {
            return (C[i - 1] * C_SCALE) / Mi;
        }
    }
}

// ---------------------------------------------------------------------------
// ONE fused kernel: 2048 blocks x 256 threads (R2 geometry).
// ---------------------------------------------------------------------------
__global__ void __launch_bounds__(SIZE, 4)
fused_kernel(const float* __restrict__ t,
             const float* __restrict__ y,
             const float* __restrict__ K,
             const float* __restrict__ C,
             const float* __restrict__ M,
             float* __restrict__ out) {
    __shared__ float sm[SIZE];   // [u(128) | v(128)]
    int b   = blockIdx.x;
    int tid = threadIdx.x;

    // ---- Part A: ydot for row b -------------------------------------------
    sm[tid] = y[b * SIZE + tid];

    // ---- Part B prologue: this thread's 4 float4 of its Jb segment --------
    int s = b & (SEGS - 1);
    int g = b >> 4;
    int segBase = s * SEG_F4;                  // float4 index within one copy

    float4 jr[4];
    #pragma unroll
    for (int q = 0; q < 4; q++) {
        int e = (segBase + q * 256 + tid) * 4; // linear float index in Jb
        int r = e >> 8;
        int c = e & (SIZE - 1);
        jr[q].x = jb_val(r, c + 0, K, C, M);
        jr[q].y = jb_val(r, c + 1, K, C, M);
        jr[q].z = jb_val(r, c + 2, K, C, M);
        jr[q].w = jb_val(r, c + 3, K, C, M);
    }

    __syncthreads();

    // ---- Part A compute + store -------------------------------------------
    float res;
    if (tid < HALF) {
        res = sm[HALF + tid];                  // ydot[:half] = v
    } else {
        int i = tid - HALF;
        float Mi = M[i] * M_SCALE;
        float acc = 0.0f;
        if (i < HALF - 1) {
            float f = K[i] * (sm[i + 1] - sm[i])
                    + (C[i] * C_SCALE) * (sm[HALF + i + 1] - sm[HALF + i]);
            acc += f / Mi;
        }
        if (i > 0) {
            float fm = K[i - 1] * (sm[i] - sm[i - 1])
                     + (C[i - 1] * C_SCALE) * (sm[HALF + i] - sm[HALF + i - 1]);
            acc -= fm / Mi;
        }
        if (i == HALF - 1) {
            acc -= (K[HALF - 1] * sm[HALF - 1]
                  + (C[HALF - 1] * C_SCALE) * sm[SIZE - 1]) / Mi;
        }
        if (i == 0) {
            acc += sinf(t[b]) / Mi;
        }
        res = acc;
    }
    out[b * SIZE + tid] = res;

    // ---- Part B: broadcast J, FULLY UNROLLED ------------------------------
    // Single base pointer; all 64 STG.128 use compile-time immediate offsets
    // (k*COPY_F4 + q*256 float4 = k*256KB + q*4KB bytes, max ~4MB: fits imm).
    float4* __restrict__ base =
        reinterpret_cast<float4*>(out + YDOT_FLOATS)
        + (long long)(g * CPB) * COPY_F4 + segBase + tid;

    #pragma unroll
    for (int k = 0; k < CPB; k++) {
        #pragma unroll
        for (int q = 0; q < 4; q++) {
            base[k * COPY_F4 + q * 256] = jr[q];
        }
    }
}

// ---------------------------------------------------------------------------
extern "C" void kernel_launch(void* const* d_in, const int* in_sizes, int n_in,
                              void* d_out, int out_size) {
    const float* t = (const float*)d_in[0];
    const float* y = (const float*)d_in[1];
    const float* K = (const float*)d_in[2];
    const float* C = (const float*)d_in[3];
    const float* M = (const float*)d_in[4];
    float* out = (float*)d_out;

    fused_kernel<<<NBLK, SIZE>>>(t, y, K, C, M, out);
}

// round 10
// speedup vs baseline: 1.0807x; 1.0392x over previous
#include <cuda_runtime.h>
#include <math.h>

// Problem constants
#define NCHUNK 32
#define NBATCH 64
#define HALF   128
#define SIZE   (2 * HALF)            // 256
#define NROWS  (NCHUNK * NBATCH)     // 2048
#define C_SCALE 1e-4f
#define M_SCALE 1e-5f

#define YDOT_FLOATS (NROWS * SIZE)   // 524288

// R2 geometry (measured best): 16 segments x 128 groups = 2048 blocks.
// Each block holds one 16KB segment (4 float4/thread in registers) and
// writes it to 16 CONTIGUOUS batch copies with unroll-4 STG.128 streams.
// R9 delta: streaming (.cs evict-first) stores for the write-once J data.
#define SEGS 16
#define GRP  128
#define NBLK (SEGS * GRP)            // 2048
#define CPB  (NROWS / GRP)           // 16 copies per block
#define SEG_F4 1024                  // float4 per segment
#define COPY_F4 16384                // float4 per J copy

// ---------------------------------------------------------------------------
// Closed-form Jb[r][c] (256x256)
// ---------------------------------------------------------------------------
__device__ __forceinline__ float jb_val(int r, int c,
                                        const float* __restrict__ K,
                                        const float* __restrict__ C,
                                        const float* __restrict__ M) {
    if (r < HALF) {
        return (c == r + HALF) ? 1.0f : 0.0f;
    }
    int i = r - HALF;
    int j = (c < HALF) ? c : (c - HALF);
    int d = j - i;
    if (d < -1 || d > 1) return 0.0f;

    float Mi = M[i] * M_SCALE;
    if (c < HALF) {
        if (d == 0) {
            float v = -K[i] / Mi;
            if (i > 0) v -= K[i - 1] / Mi;
            return v;
        } else if (d == 1) {
            return K[i] / Mi;
        } else {
            return K[i - 1] / Mi;
        }
    } else {
        if (d == 0) {
            float v = -(C[i] * C_SCALE) / Mi;
            if (i > 0) v -= (C[i - 1] * C_SCALE) / Mi;
            return v;
        } else if (d == 1) {
            return (C[i] * C_SCALE) / Mi;
        } else {
            return (C[i - 1] * C_SCALE) / Mi;
        }
    }
}

// ---------------------------------------------------------------------------
// ONE fused kernel: 2048 blocks x 256 threads (R2 geometry).
// ---------------------------------------------------------------------------
__global__ void __launch_bounds__(SIZE, 4)
fused_kernel(const float* __restrict__ t,
             const float* __restrict__ y,
             const float* __restrict__ K,
             const float* __restrict__ C,
             const float* __restrict__ M,
             float* __restrict__ out) {
    __shared__ float sm[SIZE];   // [u(128) | v(128)]
    int b   = blockIdx.x;
    int tid = threadIdx.x;

    // ---- Part A: ydot for row b -------------------------------------------
    sm[tid] = y[b * SIZE + tid];

    // ---- Part B prologue: this thread's 4 float4 of its Jb segment --------
    int s = b & (SEGS - 1);
    int g = b >> 4;
    int segBase = s * SEG_F4;                  // float4 index within one copy

    float4 jr[4];
    #pragma unroll
    for (int q = 0; q < 4; q++) {
        int e = (segBase + q * 256 + tid) * 4; // linear float index in Jb
        int r = e >> 8;
        int c = e & (SIZE - 1);
        jr[q].x = jb_val(r, c + 0, K, C, M);
        jr[q].y = jb_val(r, c + 1, K, C, M);
        jr[q].z = jb_val(r, c + 2, K, C, M);
        jr[q].w = jb_val(r, c + 3, K, C, M);
    }

    __syncthreads();

    // ---- Part A compute + store -------------------------------------------
    float res;
    if (tid < HALF) {
        res = sm[HALF + tid];                  // ydot[:half] = v
    } else {
        int i = tid - HALF;
        float Mi = M[i] * M_SCALE;
        float acc = 0.0f;
        if (i < HALF - 1) {
            float f = K[i] * (sm[i + 1] - sm[i])
                    + (C[i] * C_SCALE) * (sm[HALF + i + 1] - sm[HALF + i]);
            acc += f / Mi;
        }
        if (i > 0) {
            float fm = K[i - 1] * (sm[i] - sm[i - 1])
                     + (C[i - 1] * C_SCALE) * (sm[HALF + i] - sm[HALF + i - 1]);
            acc -= fm / Mi;
        }
        if (i == HALF - 1) {
            acc -= (K[HALF - 1] * sm[HALF - 1]
                  + (C[HALF - 1] * C_SCALE) * sm[SIZE - 1]) / Mi;
        }
        if (i == 0) {
            acc += sinf(t[b]) / Mi;
        }
        res = acc;
    }
    out[b * SIZE + tid] = res;

    // ---- Part B: broadcast J (register replay, streaming STG.128) ---------
    float4* __restrict__ j4 = reinterpret_cast<float4*>(out + YDOT_FLOATS);
    int c0 = g * CPB;
    #pragma unroll 4
    for (int k = 0; k < CPB; k++) {
        float4* dst = j4 + (long long)(c0 + k) * 16384 + segBase + tid;
        __stcs(dst + 0 * 256, jr[0]);
        __stcs(dst + 1 * 256, jr[1]);
        __stcs(dst + 2 * 256, jr[2]);
        __stcs(dst + 3 * 256, jr[3]);
    }
}

// ---------------------------------------------------------------------------
extern "C" void kernel_launch(void* const* d_in, const int* in_sizes, int n_in,
                              void* d_out, int out_size) {
    const float* t = (const float*)d_in[0];
    const float* y = (const float*)d_in[1];
    const float* K = (const float*)d_in[2];
    const float* C = (const float*)d_in[3];
    const float* M = (const float*)d_in[4];
    float* out = (float*)d_out;

    fused_kernel<<<NBLK, SIZE>>>(t, y, K, C, M, out);
}